// round 1
// baseline (speedup 1.0000x reference)
#include <cuda_runtime.h>
#include <cstdint>

// Problem constants
#define NB    2048
#define TT    128
#define FF    64
#define HH    256
#define OUTL  32
#define BT    16            // batch rows per CTA
#define NCTA  (NB / BT)     // 128
#define NTHR  256

// Encoder hidden states, needed by decoder attention: [B][T][H] fp32 (256 MB scratch)
__device__ float g_hs[(size_t)NB * TT * HH];

typedef unsigned long long u64;

// Packed fp32x2 FMA (Blackwell FFMA2 — only reachable via PTX fma.rn.f32x2)
__device__ __forceinline__ u64 fma2(u64 a, u64 b, u64 c) {
    u64 d;
    asm("fma.rn.f32x2 %0, %1, %2, %3;" : "=l"(d) : "l"(a), "l"(b), "l"(c));
    return d;
}
__device__ __forceinline__ float hsum2(u64 a) {
    float lo = __int_as_float((int)(unsigned)(a & 0xffffffffull));
    float hi = __int_as_float((int)(unsigned)(a >> 32));
    return lo + hi;
}
__device__ __forceinline__ float sigf(float x) {
    return __fdividef(1.f, 1.f + __expf(-x));
}
__device__ __forceinline__ float tanh_f(float x) {
    // tanh(x) = 2*sigmoid(2x) - 1  (fast-exp based, ~1e-6 rel err)
    return 2.f * sigf(2.f * x) - 1.f;
}

struct SM {
    float hbuf[2][BT][HH];   // encoder: double-buffered h; decoder: [0]=ctx, [1]=hd
    float xs[BT][FF];        // x tile for current timestep
    float A[BT][TT];         // Wq . hs[b][t]
    float Cc[BT][TT];        // bq . hs[b][t]
    float ww[BT][TT];        // softmax weights per decoder step
    float ctxp[2][BT][HH];   // ctx partial sums (two t-halves)
    float wq[HH];
    float bq[HH];
    float prevs[BT];
    float wpart[8][BT];      // fc2 cross-warp reduction
};

__global__ void __launch_bounds__(NTHR, 1)
attentive_forecaster_kernel(
    const float* __restrict__ x,     const float* __restrict__ h0,
    const float* __restrict__ eWih,  const float* __restrict__ eWhh,
    const float* __restrict__ ebih,  const float* __restrict__ ebhh,
    const float* __restrict__ dWih,  const float* __restrict__ dWhh,
    const float* __restrict__ dbih,  const float* __restrict__ dbhh,
    const float* __restrict__ aWq,   const float* __restrict__ abq,
    const float* __restrict__ f1W,   const float* __restrict__ f1b,
    const float* __restrict__ f2W,   const float* __restrict__ f2b,
    float* __restrict__ out)
{
    extern __shared__ char smraw[];
    SM* sm = (SM*)smraw;
    const int tid  = threadIdx.x;
    const int wid  = tid >> 5;
    const int lane = tid & 31;
    const int b0   = blockIdx.x * BT;

    // ---- preload h0 tile + attention query vectors into smem ----
    for (int i = tid; i < BT * HH; i += NTHR)
        ((float*)sm->hbuf[0])[i] = h0[(size_t)b0 * HH + i];
    for (int i = tid; i < HH; i += NTHR) { sm->wq[i] = aWq[i]; sm->bq[i] = abq[i]; }

    // per-thread cached encoder biases (thread tid owns hidden unit tid)
    const float ebR  = ebih[tid]          + ebhh[tid];
    const float ebZ  = ebih[tid + HH]     + ebhh[tid + HH];
    const float ebNi = ebih[tid + 2*HH];
    const float ebNh = ebhh[tid + 2*HH];

    const float* wrI = eWih + (size_t)tid * FF;
    const float* wzI = eWih + (size_t)(tid + HH) * FF;
    const float* wnI = eWih + (size_t)(tid + 2*HH) * FF;
    const float* wrH = eWhh + (size_t)tid * HH;
    const float* wzH = eWhh + (size_t)(tid + HH) * HH;
    const float* wnH = eWhh + (size_t)(tid + 2*HH) * HH;

    __syncthreads();

    // ======================= ENCODER =======================
    int cur = 0;
    for (int t = 0; t < TT; t++) {
        // load x[:, t, :] tile (one float4 per thread, coalesced)
        {
            int b = tid >> 4, f4 = tid & 15;
            *(float4*)&sm->xs[b][f4 * 4] =
                *(const float4*)&x[((size_t)(b0 + b) * TT + t) * FF + f4 * 4];
        }
        __syncthreads();

        u64 accR[BT], accZ[BT], accN[BT];
        #pragma unroll
        for (int b = 0; b < BT; b++) { accR[b] = 0; accZ[b] = 0; accN[b] = 0; }

        // gi = x_t @ Wih^T  (k < 64)
        #pragma unroll 2
        for (int k = 0; k < FF; k += 4) {
            ulonglong2 wr = *(const ulonglong2*)(wrI + k);
            ulonglong2 wz = *(const ulonglong2*)(wzI + k);
            ulonglong2 wn = *(const ulonglong2*)(wnI + k);
            #pragma unroll
            for (int b = 0; b < BT; b++) {
                ulonglong2 xv = *(const ulonglong2*)&sm->xs[b][k];
                accR[b] = fma2(wr.x, xv.x, accR[b]); accR[b] = fma2(wr.y, xv.y, accR[b]);
                accZ[b] = fma2(wz.x, xv.x, accZ[b]); accZ[b] = fma2(wz.y, xv.y, accZ[b]);
                accN[b] = fma2(wn.x, xv.x, accN[b]); accN[b] = fma2(wn.y, xv.y, accN[b]);
            }
        }
        float ni[BT];
        #pragma unroll
        for (int b = 0; b < BT; b++) { ni[b] = hsum2(accN[b]); accN[b] = 0; }

        // gh = h @ Whh^T  (k < 256)
        #pragma unroll 2
        for (int k = 0; k < HH; k += 4) {
            ulonglong2 wr = *(const ulonglong2*)(wrH + k);
            ulonglong2 wz = *(const ulonglong2*)(wzH + k);
            ulonglong2 wn = *(const ulonglong2*)(wnH + k);
            #pragma unroll
            for (int b = 0; b < BT; b++) {
                ulonglong2 hv = *(const ulonglong2*)&sm->hbuf[cur][b][k];
                accR[b] = fma2(wr.x, hv.x, accR[b]); accR[b] = fma2(wr.y, hv.y, accR[b]);
                accZ[b] = fma2(wz.x, hv.x, accZ[b]); accZ[b] = fma2(wz.y, hv.y, accZ[b]);
                accN[b] = fma2(wn.x, hv.x, accN[b]); accN[b] = fma2(wn.y, hv.y, accN[b]);
            }
        }

        const int nxt = cur ^ 1;
        #pragma unroll
        for (int b = 0; b < BT; b++) {
            float r  = sigf(hsum2(accR[b]) + ebR);
            float z  = sigf(hsum2(accZ[b]) + ebZ);
            float n  = tanh_f(ni[b] + ebNi + r * (hsum2(accN[b]) + ebNh));
            float hp = sm->hbuf[cur][b][tid];
            float hn = (1.f - z) * n + z * hp;
            sm->hbuf[nxt][b][tid] = hn;
            g_hs[((size_t)(b0 + b) * TT + t) * HH + tid] = hn;   // coalesced over tid
        }
        __syncthreads();

        // fold attention projections: A[b][t] = Wq.h_t, C[b][t] = bq.h_t  (warp per 2 rows)
        #pragma unroll
        for (int bb = 0; bb < 2; bb++) {
            int b = wid * 2 + bb;
            float pa = 0.f, pc = 0.f;
            #pragma unroll
            for (int i = 0; i < 8; i++) {
                int k = lane + 32 * i;
                float hv = sm->hbuf[nxt][b][k];
                pa += sm->wq[k] * hv;
                pc += sm->bq[k] * hv;
            }
            #pragma unroll
            for (int off = 16; off; off >>= 1) {
                pa += __shfl_down_sync(0xffffffffu, pa, off);
                pc += __shfl_down_sync(0xffffffffu, pc, off);
            }
            if (lane == 0) { sm->A[b][t] = pa; sm->Cc[b][t] = pc; }
        }
        cur = nxt;
        __syncthreads();
    }

    // ======================= DECODER =======================
    const float dbR  = dbih[tid]          + dbhh[tid];
    const float dbZ  = dbih[tid + HH]     + dbhh[tid + HH];
    const float dbNi = dbih[tid + 2*HH];
    const float dbNh = dbhh[tid + 2*HH];
    const float wiR  = dWih[tid];
    const float wiZ  = dWih[tid + HH];
    const float wiN  = dWih[tid + 2*HH];
    const float f2w  = f2W[tid];
    const float f1bv = f1b[tid];
    const float f2b0 = f2b[0];
    const float* wrD   = dWhh + (size_t)tid * HH;
    const float* wzD   = dWhh + (size_t)(tid + HH) * HH;
    const float* wnD   = dWhh + (size_t)(tid + 2*HH) * HH;
    const float* f1row = f1W  + (size_t)tid * HH;

    if (tid < BT)
        sm->prevs[tid] = x[((size_t)(b0 + tid) * TT + (TT - 1)) * FF + 0];
    __syncthreads();

    const float scale = 0.0625f;  // 1/sqrt(H)
    float* ctx = (float*)sm->hbuf[0];  // [BT][HH]
    float* hd  = (float*)sm->hbuf[1];  // [BT][HH]

    for (int s = 0; s < OUTL; s++) {
        // ---- scores + softmax (scores = prev*A + C, no hs traffic) ----
        #pragma unroll
        for (int bb = 0; bb < 2; bb++) {
            int b = wid * 2 + bb;
            float p = sm->prevs[b];
            float sc[4];
            float mx = -1e30f;
            #pragma unroll
            for (int i = 0; i < 4; i++) {
                int t = lane + 32 * i;
                sc[i] = (p * sm->A[b][t] + sm->Cc[b][t]) * scale;
                mx = fmaxf(mx, sc[i]);
            }
            #pragma unroll
            for (int off = 16; off; off >>= 1) mx = fmaxf(mx, __shfl_xor_sync(0xffffffffu, mx, off));
            float sum = 0.f;
            #pragma unroll
            for (int i = 0; i < 4; i++) { sc[i] = __expf(sc[i] - mx); sum += sc[i]; }
            #pragma unroll
            for (int off = 16; off; off >>= 1) sum += __shfl_xor_sync(0xffffffffu, sum, off);
            float inv = __fdividef(1.f, sum);
            #pragma unroll
            for (int i = 0; i < 4; i++) sm->ww[b][lane + 32 * i] = sc[i] * inv;
        }
        __syncthreads();

        // ---- ctx = sum_t w[t] * hs[t]  (streams g_hs, coalesced float2) ----
        {
            int tq = tid >> 7;            // t-half: 0 or 1
            int c2 = (tid & 127) * 2;     // this thread's 2 h-columns
            float2 acc[BT];
            #pragma unroll
            for (int b = 0; b < BT; b++) acc[b] = make_float2(0.f, 0.f);
            #pragma unroll 1
            for (int ti = 0; ti < TT / 2; ti++) {
                int t = tq * (TT / 2) + ti;
                const float* hsrow = &g_hs[((size_t)b0 * TT + t) * HH + c2];
                #pragma unroll
                for (int b = 0; b < BT; b++) {
                    float  wv = sm->ww[b][t];
                    float2 hv = *(const float2*)(hsrow + (size_t)b * TT * HH);
                    acc[b].x += wv * hv.x;
                    acc[b].y += wv * hv.y;
                }
            }
            #pragma unroll
            for (int b = 0; b < BT; b++) *(float2*)&sm->ctxp[tq][b][c2] = acc[b];
        }
        __syncthreads();
        for (int i = tid; i < BT * HH; i += NTHR)
            ctx[i] = ((float*)sm->ctxp[0])[i] + ((float*)sm->ctxp[1])[i];
        __syncthreads();

        // ---- decoder GRU cell: gh = ctx @ dWhh^T ----
        {
            u64 accR[BT], accZ[BT], accN[BT];
            #pragma unroll
            for (int b = 0; b < BT; b++) { accR[b] = 0; accZ[b] = 0; accN[b] = 0; }
            #pragma unroll 2
            for (int k = 0; k < HH; k += 4) {
                ulonglong2 wr = *(const ulonglong2*)(wrD + k);
                ulonglong2 wz = *(const ulonglong2*)(wzD + k);
                ulonglong2 wn = *(const ulonglong2*)(wnD + k);
                #pragma unroll
                for (int b = 0; b < BT; b++) {
                    ulonglong2 hv = *(const ulonglong2*)&ctx[b * HH + k];
                    accR[b] = fma2(wr.x, hv.x, accR[b]); accR[b] = fma2(wr.y, hv.y, accR[b]);
                    accZ[b] = fma2(wz.x, hv.x, accZ[b]); accZ[b] = fma2(wz.y, hv.y, accZ[b]);
                    accN[b] = fma2(wn.x, hv.x, accN[b]); accN[b] = fma2(wn.y, hv.y, accN[b]);
                }
            }
            #pragma unroll
            for (int b = 0; b < BT; b++) {
                float pv = sm->prevs[b];
                float r  = sigf(hsum2(accR[b]) + pv * wiR + dbR);
                float z  = sigf(hsum2(accZ[b]) + pv * wiZ + dbZ);
                float n  = tanh_f(pv * wiN + dbNi + r * (hsum2(accN[b]) + dbNh));
                float c  = ctx[b * HH + tid];
                hd[b * HH + tid] = (1.f - z) * n + z * c;
            }
        }
        __syncthreads();

        // ---- fc1(relu) + fc2 ----
        {
            u64 accF[BT];
            #pragma unroll
            for (int b = 0; b < BT; b++) accF[b] = 0;
            #pragma unroll 2
            for (int k = 0; k < HH; k += 4) {
                ulonglong2 wv = *(const ulonglong2*)(f1row + k);
                #pragma unroll
                for (int b = 0; b < BT; b++) {
                    ulonglong2 hv = *(const ulonglong2*)&hd[b * HH + k];
                    accF[b] = fma2(wv.x, hv.x, accF[b]);
                    accF[b] = fma2(wv.y, hv.y, accF[b]);
                }
            }
            #pragma unroll
            for (int b = 0; b < BT; b++) {
                float z1 = fmaxf(hsum2(accF[b]) + f1bv, 0.f);
                float v  = z1 * f2w;
                #pragma unroll
                for (int off = 16; off; off >>= 1) v += __shfl_down_sync(0xffffffffu, v, off);
                if (lane == 0) sm->wpart[wid][b] = v;
            }
        }
        __syncthreads();
        if (tid < BT) {
            float o = f2b0;
            #pragma unroll
            for (int w = 0; w < 8; w++) o += sm->wpart[w][tid];
            out[(size_t)(b0 + tid) * OUTL + s] = o;
            sm->prevs[tid] = o;
        }
        __syncthreads();
    }
}

extern "C" void kernel_launch(void* const* d_in, const int* in_sizes, int n_in,
                              void* d_out, int out_size) {
    const float* x     = (const float*)d_in[0];
    const float* h0    = (const float*)d_in[1];
    const float* eWih  = (const float*)d_in[2];
    const float* eWhh  = (const float*)d_in[3];
    const float* ebih  = (const float*)d_in[4];
    const float* ebhh  = (const float*)d_in[5];
    const float* dWih  = (const float*)d_in[6];
    const float* dWhh  = (const float*)d_in[7];
    const float* dbih  = (const float*)d_in[8];
    const float* dbhh  = (const float*)d_in[9];
    const float* aWq   = (const float*)d_in[10];
    const float* abq   = (const float*)d_in[11];
    const float* f1W   = (const float*)d_in[12];
    const float* f1b   = (const float*)d_in[13];
    const float* f2W   = (const float*)d_in[14];
    const float* f2b   = (const float*)d_in[15];
    float* out = (float*)d_out;

    size_t shmem = sizeof(SM);
    cudaFuncSetAttribute(attentive_forecaster_kernel,
                         cudaFuncAttributeMaxDynamicSharedMemorySize, (int)shmem);
    attentive_forecaster_kernel<<<NCTA, NTHR, shmem>>>(
        x, h0, eWih, eWhh, ebih, ebhh, dWih, dWhh, dbih, dbhh,
        aWq, abq, f1W, f1b, f2W, f2b, out);
}

// round 3
// speedup vs baseline: 1.1629x; 1.1629x over previous
#include <cuda_runtime.h>
#include <cuda_fp16.h>
#include <cstdint>

#define NB    2048
#define TT    128
#define FF    64
#define HH    256
#define OUTL  32
#define BT    16
#define NCTA  (NB / BT)
#define NTHR  256
#define ROWP  20          // padded row stride (floats) for transposed smem tiles

// Transposed weights (one-time prep): Wt[k][j]
__device__ float  g_WtI[FF * 768];
__device__ float  g_WtE[HH * 768];
__device__ float  g_WtD[HH * 768];
__device__ float  g_Wt1[HH * HH];
// Encoder hidden states for attention, fp16: [B][T][H]
__device__ __half g_hs[(size_t)NB * TT * HH];

typedef unsigned long long u64;

__device__ __forceinline__ u64 fma2(u64 a, u64 b, u64 c) {
    u64 d;
    asm("fma.rn.f32x2 %0, %1, %2, %3;" : "=l"(d) : "l"(a), "l"(b), "l"(c));
    return d;
}
__device__ __forceinline__ u64 dup2(float w) {
    unsigned r = __float_as_uint(w);
    u64 d;
    asm("mov.b64 %0, {%1, %1};" : "=l"(d) : "r"(r));
    return d;
}
__device__ __forceinline__ float2 unpk(u64 a) {
    unsigned lo, hi;
    asm("mov.b64 {%0, %1}, %2;" : "=r"(lo), "=r"(hi) : "l"(a));
    return make_float2(__uint_as_float(lo), __uint_as_float(hi));
}
__device__ __forceinline__ float sigf(float x) {
    return __fdividef(1.f, 1.f + __expf(-x));
}
__device__ __forceinline__ float tanh_f(float x) {
    return 2.f * sigf(2.f * x) - 1.f;
}

// ---- one-time weight transpose ----
__global__ void prep_kernel(const float* __restrict__ eWih, const float* __restrict__ eWhh,
                            const float* __restrict__ dWhh, const float* __restrict__ f1W) {
    const int n1 = FF * 768, n2 = HH * 768, n3 = HH * 768, n4 = HH * HH;
    for (int i = blockIdx.x * blockDim.x + threadIdx.x; i < n1 + n2 + n3 + n4;
         i += gridDim.x * blockDim.x) {
        if (i < n1) {
            int k = i / 768, j = i % 768;
            g_WtI[i] = eWih[(size_t)j * FF + k];
        } else if (i < n1 + n2) {
            int r = i - n1, k = r / 768, j = r % 768;
            g_WtE[r] = eWhh[(size_t)j * HH + k];
        } else if (i < n1 + n2 + n3) {
            int r = i - n1 - n2, k = r / 768, j = r % 768;
            g_WtD[r] = dWhh[(size_t)j * HH + k];
        } else {
            int r = i - n1 - n2 - n3, k = r / HH, j = r % HH;
            g_Wt1[r] = f1W[(size_t)j * HH + k];
        }
    }
}

struct SM {
    float hti[2][HH][ROWP];   // transposed h tiles [k][b]; decoder: [1]=ctx, [0]=hd
    float xti[FF][ROWP];      // transposed x tile
    float A[BT][TT];          // Wq . hs
    float C[BT][TT];          // bq . hs
    float ww[BT][TT];         // softmax weights
    float ctxp[2][BT][HH];    // ctx partials [t-half][b][c]
    float ApC[2][8][BT];      // A/C warp partials
    float wpart[8][BT];       // fc2 warp partials
    float prevs[BT];
};

__global__ void __launch_bounds__(NTHR, 1)
forecaster_kernel(
    const float* __restrict__ x,     const float* __restrict__ h0,
    const float* __restrict__ ebih,  const float* __restrict__ ebhh,
    const float* __restrict__ dWih,  const float* __restrict__ dbih,
    const float* __restrict__ dbhh,  const float* __restrict__ aWq,
    const float* __restrict__ abq,   const float* __restrict__ f1b,
    const float* __restrict__ f2W,   const float* __restrict__ f2b,
    float* __restrict__ out)
{
    extern __shared__ char smraw[];
    SM* sm = (SM*)smraw;
    const int tid = threadIdx.x, wid = tid >> 5, lane = tid & 31;
    const int b0 = blockIdx.x * BT;

    // init hti[0] = h0 transposed
    for (int i = tid; i < BT * HH; i += NTHR) {
        int b = i >> 8, k = i & 255;
        sm->hti[0][k][b] = h0[(size_t)(b0 + b) * HH + k];
    }

    const float ebR  = ebih[tid]          + ebhh[tid];
    const float ebZ  = ebih[tid + HH]     + ebhh[tid + HH];
    const float ebNi = ebih[tid + 2 * HH];
    const float ebNh = ebhh[tid + 2 * HH];
    const float wqv  = aWq[tid];
    const float bqv  = abq[tid];

    // ======================= ENCODER =======================
    int cur = 0;
    for (int t = 0; t < TT; t++) {
        {   // stage x tile transposed
            int b = tid >> 4, k4 = (tid & 15) * 4;
            float4 xv = *(const float4*)&x[((size_t)(b0 + b) * TT + t) * FF + k4];
            sm->xti[k4 + 0][b] = xv.x; sm->xti[k4 + 1][b] = xv.y;
            sm->xti[k4 + 2][b] = xv.z; sm->xti[k4 + 3][b] = xv.w;
        }
        __syncthreads();

        u64 aR[8], aZ[8], aN[8];
        #pragma unroll
        for (int p = 0; p < 8; p++) { aR[p] = 0; aZ[p] = 0; aN[p] = 0; }

        // gi = x_t @ Wih^T   (outer-product over k, coalesced weight loads)
        const float* wI = g_WtI + tid;
        #pragma unroll 4
        for (int k = 0; k < FF; k++) {
            u64 wr2 = dup2(wI[k * 768]);
            u64 wz2 = dup2(wI[k * 768 + 256]);
            u64 wn2 = dup2(wI[k * 768 + 512]);
            const u64* hp = (const u64*)sm->xti[k];
            #pragma unroll
            for (int p = 0; p < 8; p++) {
                u64 h = hp[p];
                aR[p] = fma2(wr2, h, aR[p]);
                aZ[p] = fma2(wz2, h, aZ[p]);
                aN[p] = fma2(wn2, h, aN[p]);
            }
        }
        u64 ni[8];
        #pragma unroll
        for (int p = 0; p < 8; p++) { ni[p] = aN[p]; aN[p] = 0; }

        // gh = h @ Whh^T
        const float* wE = g_WtE + tid;
        #pragma unroll 4
        for (int k = 0; k < HH; k++) {
            u64 wr2 = dup2(wE[k * 768]);
            u64 wz2 = dup2(wE[k * 768 + 256]);
            u64 wn2 = dup2(wE[k * 768 + 512]);
            const u64* hp = (const u64*)sm->hti[cur][k];
            #pragma unroll
            for (int p = 0; p < 8; p++) {
                u64 h = hp[p];
                aR[p] = fma2(wr2, h, aR[p]);
                aZ[p] = fma2(wz2, h, aZ[p]);
                aN[p] = fma2(wn2, h, aN[p]);
            }
        }

        const int nxt = cur ^ 1;
        float hn[BT];
        #pragma unroll
        for (int p = 0; p < 8; p++) {
            float2 r2 = unpk(aR[p]), z2 = unpk(aZ[p]);
            float2 nh2 = unpk(aN[p]), ni2 = unpk(ni[p]);
            float hp0 = sm->hti[cur][tid][2 * p];
            float hp1 = sm->hti[cur][tid][2 * p + 1];
            {
                float r = sigf(r2.x + ebR), z = sigf(z2.x + ebZ);
                float n = tanh_f(ni2.x + ebNi + r * (nh2.x + ebNh));
                hn[2 * p] = (1.f - z) * n + z * hp0;
            }
            {
                float r = sigf(r2.y + ebR), z = sigf(z2.y + ebZ);
                float n = tanh_f(ni2.y + ebNi + r * (nh2.y + ebNh));
                hn[2 * p + 1] = (1.f - z) * n + z * hp1;
            }
        }
        #pragma unroll
        for (int q = 0; q < 4; q++)
            *(float4*)&sm->hti[nxt][tid][4 * q] =
                make_float4(hn[4 * q], hn[4 * q + 1], hn[4 * q + 2], hn[4 * q + 3]);
        #pragma unroll
        for (int b = 0; b < BT; b++)
            g_hs[((size_t)(b0 + b) * TT + t) * HH + tid] = __float2half(hn[b]);

        // fold A[b][t]=Wq.h, C[b][t]=bq.h  (butterfly over warp, combine across warps)
        #pragma unroll
        for (int b = 0; b < BT; b++) {
            float pa = wqv * hn[b], pc = bqv * hn[b];
            #pragma unroll
            for (int off = 16; off; off >>= 1) {
                pa += __shfl_xor_sync(0xffffffffu, pa, off);
                pc += __shfl_xor_sync(0xffffffffu, pc, off);
            }
            if (lane == 0) { sm->ApC[0][wid][b] = pa; sm->ApC[1][wid][b] = pc; }
        }
        __syncthreads();
        if (tid < 32) {
            int b = tid & 15, sel = tid >> 4;
            float s = 0.f;
            #pragma unroll
            for (int w = 0; w < 8; w++) s += sm->ApC[sel][w][b];
            if (sel) sm->C[b][t] = s; else sm->A[b][t] = s;
        }
        cur = nxt;
    }

    // ======================= DECODER =======================
    const float dbR  = dbih[tid]          + dbhh[tid];
    const float dbZ  = dbih[tid + HH]     + dbhh[tid + HH];
    const float dbNi = dbih[tid + 2 * HH];
    const float dbNh = dbhh[tid + 2 * HH];
    const float wiR  = dWih[tid];
    const float wiZ  = dWih[tid + HH];
    const float wiN  = dWih[tid + 2 * HH];
    const float f2w  = f2W[tid];
    const float f1bv = f1b[tid];
    const float f2b0 = f2b[0];

    if (tid < BT)
        sm->prevs[tid] = x[((size_t)(b0 + tid) * TT + (TT - 1)) * FF];
    __syncthreads();

    const float scale = 0.0625f;
    for (int s = 0; s < OUTL; s++) {
        // scores + softmax  (scores = prev*A + C; warp per 2 batch rows)
        #pragma unroll
        for (int bb = 0; bb < 2; bb++) {
            int b = wid * 2 + bb;
            float p = sm->prevs[b];
            float sc[4]; float mx = -1e30f;
            #pragma unroll
            for (int i = 0; i < 4; i++) {
                int tt2 = lane + 32 * i;
                sc[i] = (p * sm->A[b][tt2] + sm->C[b][tt2]) * scale;
                mx = fmaxf(mx, sc[i]);
            }
            #pragma unroll
            for (int off = 16; off; off >>= 1)
                mx = fmaxf(mx, __shfl_xor_sync(0xffffffffu, mx, off));
            float sum = 0.f;
            #pragma unroll
            for (int i = 0; i < 4; i++) { sc[i] = __expf(sc[i] - mx); sum += sc[i]; }
            #pragma unroll
            for (int off = 16; off; off >>= 1)
                sum += __shfl_xor_sync(0xffffffffu, sum, off);
            float inv = __fdividef(1.f, sum);
            #pragma unroll
            for (int i = 0; i < 4; i++) sm->ww[b][lane + 32 * i] = sc[i] * inv;
        }
        __syncthreads();

        // ctx = sum_t w[t]*hs[t]  (fp16 stream, coalesced half2)
        {
            int th = tid >> 7, c = (tid & 127) * 2;
            float2 acc[BT];
            #pragma unroll
            for (int b = 0; b < BT; b++) acc[b] = make_float2(0.f, 0.f);
            const __half* base = g_hs + ((size_t)b0 * TT + th * 64) * HH + c;
            #pragma unroll 1
            for (int ti = 0; ti < 64; ti++) {
                int tt2 = th * 64 + ti;
                const __half* pb = base + (size_t)ti * HH;
                #pragma unroll
                for (int b = 0; b < BT; b++) {
                    float wv = sm->ww[b][tt2];
                    __half2 hv = *(const __half2*)(pb + (size_t)b * TT * HH);
                    float2 f = __half22float2(hv);
                    acc[b].x = fmaf(wv, f.x, acc[b].x);
                    acc[b].y = fmaf(wv, f.y, acc[b].y);
                }
            }
            #pragma unroll
            for (int b = 0; b < BT; b++)
                *(float2*)&sm->ctxp[th][b][c] = acc[b];
        }
        __syncthreads();
        {   // combine halves into transposed ctx tile (hti[1])
            int k = tid;
            #pragma unroll
            for (int b = 0; b < BT; b++)
                sm->hti[1][k][b] = sm->ctxp[0][b][k] + sm->ctxp[1][b][k];
        }
        __syncthreads();

        // decoder GRU: gh = ctx @ dWhh^T (outer-product on transposed weights)
        {
            u64 aR[8], aZ[8], aN[8];
            #pragma unroll
            for (int p = 0; p < 8; p++) { aR[p] = 0; aZ[p] = 0; aN[p] = 0; }
            const float* wD = g_WtD + tid;
            #pragma unroll 4
            for (int k = 0; k < HH; k++) {
                u64 wr2 = dup2(wD[k * 768]);
                u64 wz2 = dup2(wD[k * 768 + 256]);
                u64 wn2 = dup2(wD[k * 768 + 512]);
                const u64* hp = (const u64*)sm->hti[1][k];
                #pragma unroll
                for (int p = 0; p < 8; p++) {
                    u64 h = hp[p];
                    aR[p] = fma2(wr2, h, aR[p]);
                    aZ[p] = fma2(wz2, h, aZ[p]);
                    aN[p] = fma2(wn2, h, aN[p]);
                }
            }
            float hdv[BT];
            #pragma unroll
            for (int p = 0; p < 8; p++) {
                float2 r2 = unpk(aR[p]), z2 = unpk(aZ[p]), nh2 = unpk(aN[p]);
                {
                    int b = 2 * p; float pv = sm->prevs[b];
                    float r = sigf(r2.x + pv * wiR + dbR);
                    float z = sigf(z2.x + pv * wiZ + dbZ);
                    float n = tanh_f(pv * wiN + dbNi + r * (nh2.x + dbNh));
                    hdv[b] = (1.f - z) * n + z * sm->hti[1][tid][b];
                }
                {
                    int b = 2 * p + 1; float pv = sm->prevs[b];
                    float r = sigf(r2.y + pv * wiR + dbR);
                    float z = sigf(z2.y + pv * wiZ + dbZ);
                    float n = tanh_f(pv * wiN + dbNi + r * (nh2.y + dbNh));
                    hdv[b] = (1.f - z) * n + z * sm->hti[1][tid][b];
                }
            }
            #pragma unroll
            for (int q = 0; q < 4; q++)
                *(float4*)&sm->hti[0][tid][4 * q] =
                    make_float4(hdv[4 * q], hdv[4 * q + 1], hdv[4 * q + 2], hdv[4 * q + 3]);
        }
        __syncthreads();

        // fc1(relu) + fc2
        {
            u64 aF[8];
            #pragma unroll
            for (int p = 0; p < 8; p++) aF[p] = 0;
            const float* w1 = g_Wt1 + tid;
            #pragma unroll 4
            for (int k = 0; k < HH; k++) {
                u64 w2 = dup2(w1[k * 256]);
                const u64* hp = (const u64*)sm->hti[0][k];
                #pragma unroll
                for (int p = 0; p < 8; p++)
                    aF[p] = fma2(w2, hp[p], aF[p]);
            }
            #pragma unroll
            for (int p = 0; p < 8; p++) {
                float2 f = unpk(aF[p]);
                float v0 = fmaxf(f.x + f1bv, 0.f) * f2w;
                float v1 = fmaxf(f.y + f1bv, 0.f) * f2w;
                #pragma unroll
                for (int off = 16; off; off >>= 1) {
                    v0 += __shfl_down_sync(0xffffffffu, v0, off);
                    v1 += __shfl_down_sync(0xffffffffu, v1, off);
                }
                if (lane == 0) {
                    sm->wpart[wid][2 * p]     = v0;
                    sm->wpart[wid][2 * p + 1] = v1;
                }
            }
        }
        __syncthreads();
        if (tid < BT) {
            float o = f2b0;
            #pragma unroll
            for (int w = 0; w < 8; w++) o += sm->wpart[w][tid];
            out[(size_t)(b0 + tid) * OUTL + s] = o;
            sm->prevs[tid] = o;
        }
        __syncthreads();
    }
}

extern "C" void kernel_launch(void* const* d_in, const int* in_sizes, int n_in,
                              void* d_out, int out_size) {
    const float* x    = (const float*)d_in[0];
    const float* h0   = (const float*)d_in[1];
    const float* eWih = (const float*)d_in[2];
    const float* eWhh = (const float*)d_in[3];
    const float* ebih = (const float*)d_in[4];
    const float* ebhh = (const float*)d_in[5];
    const float* dWih = (const float*)d_in[6];
    const float* dWhh = (const float*)d_in[7];
    const float* dbih = (const float*)d_in[8];
    const float* dbhh = (const float*)d_in[9];
    const float* aWq  = (const float*)d_in[10];
    const float* abq  = (const float*)d_in[11];
    const float* f1W  = (const float*)d_in[12];
    const float* f1b  = (const float*)d_in[13];
    const float* f2W  = (const float*)d_in[14];
    const float* f2b  = (const float*)d_in[15];
    float* out = (float*)d_out;

    prep_kernel<<<256, 256>>>(eWih, eWhh, dWhh, f1W);

    size_t shmem = sizeof(SM);
    cudaFuncSetAttribute(forecaster_kernel,
                         cudaFuncAttributeMaxDynamicSharedMemorySize, (int)shmem);
    forecaster_kernel<<<NCTA, NTHR, shmem>>>(
        x, h0, ebih, ebhh, dWih, dbih, dbhh, aWq, abq, f1b, f2W, f2b, out);
}

// round 4
// speedup vs baseline: 1.3971x; 1.2014x over previous
#include <cuda_runtime.h>
#include <cuda_fp16.h>
#include <cstdint>

#define NB    2048
#define TT    128
#define FF    64
#define HH    256
#define OUTL  32
#define BT    16
#define NCTA  (NB / BT)
#define NTHR  512
#define ROWP  20

// Prepped weights: [k][j] layouts, r/z packed as float2
__device__ float2 g_eRZ[FF * HH];
__device__ float  g_eN [FF * HH];
__device__ float2 g_hRZ[HH * HH];
__device__ float  g_hN [HH * HH];
__device__ float2 g_dRZ[HH * HH];
__device__ float  g_dN [HH * HH];
__device__ float  g_W1 [HH * HH];
// Encoder hidden states (fp16) for decoder attention: [B][T][H]
__device__ __half g_hs[(size_t)NB * TT * HH];

typedef unsigned long long u64;

__device__ __forceinline__ u64 fma2(u64 a, u64 b, u64 c) {
    u64 d;
    asm("fma.rn.f32x2 %0, %1, %2, %3;" : "=l"(d) : "l"(a), "l"(b), "l"(c));
    return d;
}
__device__ __forceinline__ u64 dup2(float w) {
    unsigned r = __float_as_uint(w);
    u64 d;
    asm("mov.b64 %0, {%1, %1};" : "=l"(d) : "r"(r));
    return d;
}
__device__ __forceinline__ float2 unpk(u64 a) {
    unsigned lo, hi;
    asm("mov.b64 {%0, %1}, %2;" : "=r"(lo), "=r"(hi) : "l"(a));
    return make_float2(__uint_as_float(lo), __uint_as_float(hi));
}
__device__ __forceinline__ float sigf(float x) {
    return __fdividef(1.f, 1.f + __expf(-x));
}
__device__ __forceinline__ float tanh_f(float x) {
    return 2.f * sigf(2.f * x) - 1.f;
}

__global__ void prep_kernel(const float* __restrict__ eWih, const float* __restrict__ eWhh,
                            const float* __restrict__ dWhh, const float* __restrict__ f1W) {
    int i = blockIdx.x * blockDim.x + threadIdx.x;
    if (i >= HH * HH) return;
    int k = i >> 8, j = i & 255;
    g_hRZ[i] = make_float2(eWhh[(size_t)j * HH + k], eWhh[(size_t)(j + HH) * HH + k]);
    g_hN[i]  = eWhh[(size_t)(j + 2 * HH) * HH + k];
    g_dRZ[i] = make_float2(dWhh[(size_t)j * HH + k], dWhh[(size_t)(j + HH) * HH + k]);
    g_dN[i]  = dWhh[(size_t)(j + 2 * HH) * HH + k];
    g_W1[i]  = f1W[(size_t)j * HH + k];
    if (k < FF) {
        g_eRZ[i] = make_float2(eWih[(size_t)j * FF + k], eWih[(size_t)(j + HH) * FF + k]);
        g_eN[i]  = eWih[(size_t)(j + 2 * HH) * FF + k];
    }
}

struct SM {
    float hti[2][HH][ROWP];   // transposed h tiles [k][b]; decoder: [1]=ctx, [0]=hd
    float xti[FF][ROWP];      // transposed x tile
    float A[BT][TT];          // Wq . hs
    float C[BT][TT];          // bq . hs
    float ww[BT][TT];         // softmax weights
    float ctxp[4][BT][HH];    // ctx partials [t-quarter][b][c]
    float ApC[2][16][8];      // A/C warp partials
    float wpart[16][8];       // fc2 warp partials
    float prevs[BT];
};

__global__ void __launch_bounds__(NTHR, 1)
forecaster_kernel(
    const float* __restrict__ x,     const float* __restrict__ h0,
    const float* __restrict__ ebih,  const float* __restrict__ ebhh,
    const float* __restrict__ dWih,  const float* __restrict__ dbih,
    const float* __restrict__ dbhh,  const float* __restrict__ aWq,
    const float* __restrict__ abq,   const float* __restrict__ f1b,
    const float* __restrict__ f2W,   const float* __restrict__ f2b,
    float* __restrict__ out)
{
    extern __shared__ char smraw[];
    SM* sm = (SM*)smraw;
    const int tid  = threadIdx.x, wid = tid >> 5, lane = tid & 31;
    const int j    = tid & 255;          // hidden/output unit owned by this thread
    const int bh   = tid >> 8;           // batch half (0/1)
    const int bbase = bh * 8;            // first of 8 owned batch rows
    const int b0   = blockIdx.x * BT;

    // init: h in registers + transposed tile
    float hreg[8];
    #pragma unroll
    for (int bb = 0; bb < 8; bb++) {
        float v = h0[(size_t)(b0 + bbase + bb) * HH + j];
        hreg[bb] = v;
        sm->hti[0][j][bbase + bb] = v;
    }
    const float ebR  = ebih[j]          + ebhh[j];
    const float ebZ  = ebih[j + HH]     + ebhh[j + HH];
    const float ebNi = ebih[j + 2 * HH];
    const float ebNh = ebhh[j + 2 * HH];
    const float wqv  = aWq[j];
    const float bqv  = abq[j];
    __syncthreads();

    // ======================= ENCODER =======================
    int cur = 0;
    for (int t = 0; t < TT; t++) {
        {   // stage x tile transposed (warp per batch row)
            int b = tid >> 5, k2 = (tid & 31) * 2;
            float2 xv = *(const float2*)&x[((size_t)(b0 + b) * TT + t) * FF + k2];
            sm->xti[k2][b] = xv.x; sm->xti[k2 + 1][b] = xv.y;
        }
        __syncthreads();

        u64 aR[4], aZ[4], aN[4];
        #pragma unroll
        for (int p = 0; p < 4; p++) { aR[p] = 0; aZ[p] = 0; aN[p] = 0; }

        // gi = x_t @ Wih^T
        const float2* eRZ = g_eRZ + j;
        const float*  eN  = g_eN  + j;
        #pragma unroll 4
        for (int k = 0; k < FF; k++) {
            float2 rz = eRZ[k * HH];
            u64 wr2 = dup2(rz.x), wz2 = dup2(rz.y), wn2 = dup2(eN[k * HH]);
            const u64* hp = (const u64*)&sm->xti[k][bbase];
            #pragma unroll
            for (int p = 0; p < 4; p++) {
                u64 h = hp[p];
                aR[p] = fma2(wr2, h, aR[p]);
                aZ[p] = fma2(wz2, h, aZ[p]);
                aN[p] = fma2(wn2, h, aN[p]);
            }
        }
        u64 ni[4];
        #pragma unroll
        for (int p = 0; p < 4; p++) { ni[p] = aN[p]; aN[p] = 0; }

        // gh = h @ Whh^T
        const float2* hRZ = g_hRZ + j;
        const float*  hN  = g_hN  + j;
        #pragma unroll 4
        for (int k = 0; k < HH; k++) {
            float2 rz = hRZ[k * HH];
            u64 wr2 = dup2(rz.x), wz2 = dup2(rz.y), wn2 = dup2(hN[k * HH]);
            const u64* hp = (const u64*)&sm->hti[cur][k][bbase];
            #pragma unroll
            for (int p = 0; p < 4; p++) {
                u64 h = hp[p];
                aR[p] = fma2(wr2, h, aR[p]);
                aZ[p] = fma2(wz2, h, aZ[p]);
                aN[p] = fma2(wn2, h, aN[p]);
            }
        }

        const int nxt = cur ^ 1;
        #pragma unroll
        for (int p = 0; p < 4; p++) {
            float2 r2 = unpk(aR[p]), z2 = unpk(aZ[p]);
            float2 nh2 = unpk(aN[p]), ni2 = unpk(ni[p]);
            {
                float r = sigf(r2.x + ebR), z = sigf(z2.x + ebZ);
                float n = tanh_f(ni2.x + ebNi + r * (nh2.x + ebNh));
                hreg[2 * p] = (1.f - z) * n + z * hreg[2 * p];
            }
            {
                float r = sigf(r2.y + ebR), z = sigf(z2.y + ebZ);
                float n = tanh_f(ni2.y + ebNi + r * (nh2.y + ebNh));
                hreg[2 * p + 1] = (1.f - z) * n + z * hreg[2 * p + 1];
            }
        }
        *(float4*)&sm->hti[nxt][j][bbase] =
            make_float4(hreg[0], hreg[1], hreg[2], hreg[3]);
        *(float4*)&sm->hti[nxt][j][bbase + 4] =
            make_float4(hreg[4], hreg[5], hreg[6], hreg[7]);
        #pragma unroll
        for (int bb = 0; bb < 8; bb++)
            g_hs[((size_t)(b0 + bbase + bb) * TT + t) * HH + j] = __float2half(hreg[bb]);

        // A[b][t]=Wq.h, C[b][t]=bq.h partials
        #pragma unroll
        for (int bb = 0; bb < 8; bb++) {
            float pa = wqv * hreg[bb], pc = bqv * hreg[bb];
            #pragma unroll
            for (int off = 16; off; off >>= 1) {
                pa += __shfl_xor_sync(0xffffffffu, pa, off);
                pc += __shfl_xor_sync(0xffffffffu, pc, off);
            }
            if (lane == 0) { sm->ApC[0][wid][bb] = pa; sm->ApC[1][wid][bb] = pc; }
        }
        __syncthreads();
        if (tid < 32) {
            int sel = tid >> 4, b = tid & 15;
            int wb = (b >> 3) * 8;
            float s = 0.f;
            #pragma unroll
            for (int w = 0; w < 8; w++) s += sm->ApC[sel][wb + w][b & 7];
            if (sel) sm->C[b][t] = s; else sm->A[b][t] = s;
        }
        cur = nxt;
    }

    // ======================= DECODER =======================
    const float dbR  = dbih[j]          + dbhh[j];
    const float dbZ  = dbih[j + HH]     + dbhh[j + HH];
    const float dbNi = dbih[j + 2 * HH];
    const float dbNh = dbhh[j + 2 * HH];
    const float wiR  = dWih[j];
    const float wiZ  = dWih[j + HH];
    const float wiN  = dWih[j + 2 * HH];
    const float f2w  = f2W[j];
    const float f1bv = f1b[j];
    const float f2b0 = f2b[0];

    if (tid < BT)
        sm->prevs[tid] = x[((size_t)(b0 + tid) * TT + (TT - 1)) * FF];
    __syncthreads();

    const float scale = 0.0625f;
    for (int s = 0; s < OUTL; s++) {
        // scores + softmax: warp wid handles batch row b=wid
        {
            int b = wid;
            float p = sm->prevs[b];
            float sc[4]; float mx = -1e30f;
            #pragma unroll
            for (int i = 0; i < 4; i++) {
                int tt2 = lane + 32 * i;
                sc[i] = (p * sm->A[b][tt2] + sm->C[b][tt2]) * scale;
                mx = fmaxf(mx, sc[i]);
            }
            #pragma unroll
            for (int off = 16; off; off >>= 1)
                mx = fmaxf(mx, __shfl_xor_sync(0xffffffffu, mx, off));
            float sum = 0.f;
            #pragma unroll
            for (int i = 0; i < 4; i++) { sc[i] = __expf(sc[i] - mx); sum += sc[i]; }
            #pragma unroll
            for (int off = 16; off; off >>= 1)
                sum += __shfl_xor_sync(0xffffffffu, sum, off);
            float inv = __fdividef(1.f, sum);
            #pragma unroll
            for (int i = 0; i < 4; i++) sm->ww[b][lane + 32 * i] = sc[i] * inv;
        }
        __syncthreads();

        // ctx = sum_t w[t]*hs[t] over 4 t-quarters
        {
            int th = tid >> 7, c = (tid & 127) * 2;
            float2 acc[BT];
            #pragma unroll
            for (int b = 0; b < BT; b++) acc[b] = make_float2(0.f, 0.f);
            const __half* base = g_hs + ((size_t)b0 * TT + th * 32) * HH + c;
            #pragma unroll 1
            for (int ti = 0; ti < 32; ti++) {
                int tt2 = th * 32 + ti;
                const __half* pb = base + (size_t)ti * HH;
                #pragma unroll
                for (int b = 0; b < BT; b++) {
                    float wv = sm->ww[b][tt2];
                    __half2 hv = *(const __half2*)(pb + (size_t)b * TT * HH);
                    float2 f = __half22float2(hv);
                    acc[b].x = fmaf(wv, f.x, acc[b].x);
                    acc[b].y = fmaf(wv, f.y, acc[b].y);
                }
            }
            #pragma unroll
            for (int b = 0; b < BT; b++)
                *(float2*)&sm->ctxp[th][b][c] = acc[b];
        }
        __syncthreads();
        {   // combine quarters into transposed ctx tile hti[1][k][b]
            #pragma unroll
            for (int bb = 0; bb < 8; bb++) {
                int b = bbase + bb;
                sm->hti[1][j][b] = sm->ctxp[0][b][j] + sm->ctxp[1][b][j]
                                 + sm->ctxp[2][b][j] + sm->ctxp[3][b][j];
            }
        }
        __syncthreads();

        // decoder GRU: gh = ctx @ dWhh^T
        {
            u64 aR[4], aZ[4], aN[4];
            #pragma unroll
            for (int p = 0; p < 4; p++) { aR[p] = 0; aZ[p] = 0; aN[p] = 0; }
            const float2* dRZ = g_dRZ + j;
            const float*  dN  = g_dN  + j;
            #pragma unroll 4
            for (int k = 0; k < HH; k++) {
                float2 rz = dRZ[k * HH];
                u64 wr2 = dup2(rz.x), wz2 = dup2(rz.y), wn2 = dup2(dN[k * HH]);
                const u64* hp = (const u64*)&sm->hti[1][k][bbase];
                #pragma unroll
                for (int p = 0; p < 4; p++) {
                    u64 h = hp[p];
                    aR[p] = fma2(wr2, h, aR[p]);
                    aZ[p] = fma2(wz2, h, aZ[p]);
                    aN[p] = fma2(wn2, h, aN[p]);
                }
            }
            float hdv[8];
            #pragma unroll
            for (int p = 0; p < 4; p++) {
                float2 r2 = unpk(aR[p]), z2 = unpk(aZ[p]), nh2 = unpk(aN[p]);
                {
                    int bb = 2 * p; float pv = sm->prevs[bbase + bb];
                    float r = sigf(r2.x + pv * wiR + dbR);
                    float z = sigf(z2.x + pv * wiZ + dbZ);
                    float n = tanh_f(pv * wiN + dbNi + r * (nh2.x + dbNh));
                    hdv[bb] = (1.f - z) * n + z * sm->hti[1][j][bbase + bb];
                }
                {
                    int bb = 2 * p + 1; float pv = sm->prevs[bbase + bb];
                    float r = sigf(r2.y + pv * wiR + dbR);
                    float z = sigf(z2.y + pv * wiZ + dbZ);
                    float n = tanh_f(pv * wiN + dbNi + r * (nh2.y + dbNh));
                    hdv[bb] = (1.f - z) * n + z * sm->hti[1][j][bbase + bb];
                }
            }
            __syncthreads();   // hti[1] reads done before hti[0] writes alias usage
            *(float4*)&sm->hti[0][j][bbase] =
                make_float4(hdv[0], hdv[1], hdv[2], hdv[3]);
            *(float4*)&sm->hti[0][j][bbase + 4] =
                make_float4(hdv[4], hdv[5], hdv[6], hdv[7]);
        }
        __syncthreads();

        // fc1(relu) + fc2
        {
            u64 aF[4];
            #pragma unroll
            for (int p = 0; p < 4; p++) aF[p] = 0;
            const float* w1 = g_W1 + j;
            #pragma unroll 4
            for (int k = 0; k < HH; k++) {
                u64 w2 = dup2(w1[k * HH]);
                const u64* hp = (const u64*)&sm->hti[0][k][bbase];
                #pragma unroll
                for (int p = 0; p < 4; p++)
                    aF[p] = fma2(w2, hp[p], aF[p]);
            }
            #pragma unroll
            for (int p = 0; p < 4; p++) {
                float2 f = unpk(aF[p]);
                float v0 = fmaxf(f.x + f1bv, 0.f) * f2w;
                float v1 = fmaxf(f.y + f1bv, 0.f) * f2w;
                #pragma unroll
                for (int off = 16; off; off >>= 1) {
                    v0 += __shfl_down_sync(0xffffffffu, v0, off);
                    v1 += __shfl_down_sync(0xffffffffu, v1, off);
                }
                if (lane == 0) {
                    sm->wpart[wid][2 * p]     = v0;
                    sm->wpart[wid][2 * p + 1] = v1;
                }
            }
        }
        __syncthreads();
        if (tid < BT) {
            float o = f2b0;
            int wb = (tid >> 3) * 8;
            #pragma unroll
            for (int w = 0; w < 8; w++) o += sm->wpart[wb + w][tid & 7];
            out[(size_t)(b0 + tid) * OUTL + s] = o;
            sm->prevs[tid] = o;
        }
        __syncthreads();
    }
}

extern "C" void kernel_launch(void* const* d_in, const int* in_sizes, int n_in,
                              void* d_out, int out_size) {
    const float* x    = (const float*)d_in[0];
    const float* h0   = (const float*)d_in[1];
    const float* eWih = (const float*)d_in[2];
    const float* eWhh = (const float*)d_in[3];
    const float* ebih = (const float*)d_in[4];
    const float* ebhh = (const float*)d_in[5];
    const float* dWih = (const float*)d_in[6];
    const float* dWhh = (const float*)d_in[7];
    const float* dbih = (const float*)d_in[8];
    const float* dbhh = (const float*)d_in[9];
    const float* aWq  = (const float*)d_in[10];
    const float* abq  = (const float*)d_in[11];
    const float* f1W  = (const float*)d_in[12];
    const float* f1b  = (const float*)d_in[13];
    const float* f2W  = (const float*)d_in[14];
    const float* f2b  = (const float*)d_in[15];
    float* out = (float*)d_out;

    prep_kernel<<<(HH * HH + 255) / 256, 256>>>(eWih, eWhh, dWhh, f1W);

    size_t shmem = sizeof(SM);
    cudaFuncSetAttribute(forecaster_kernel,
                         cudaFuncAttributeMaxDynamicSharedMemorySize, (int)shmem);
    forecaster_kernel<<<NCTA, NTHR, shmem>>>(
        x, h0, ebih, ebhh, dWih, dbih, dbhh, aWq, abq, f1b, f2W, f2b, out);
}

// round 5
// speedup vs baseline: 1.6688x; 1.1945x over previous
#include <cuda_runtime.h>
#include <cuda_fp16.h>
#include <cstdint>

#define NB    2048
#define TT    128
#define FF    64
#define HH    256
#define OUTL  32
#define BT    16
#define NCTA  (NB / BT)
#define NTHR  512
#define ROWP  20

// Packed weights, 2 k-rows per entry: [k2][j]
__device__ float4 g_eP4[(FF / 2) * HH];   // (r_k, z_k, r_k1, z_k1) for Wih
__device__ float2 g_eN2[(FF / 2) * HH];
__device__ float4 g_hP4[(HH / 2) * HH];   // Whh
__device__ float2 g_hN2[(HH / 2) * HH];
__device__ float4 g_dP4[(HH / 2) * HH];   // dWhh
__device__ float2 g_dN2[(HH / 2) * HH];
__device__ float2 g_W12[(HH / 2) * HH];   // f1W
// Encoder hidden states: fp32 (A/C pass) + fp16 (ctx stream)
__device__ float  g_hsf[(size_t)NB * TT * HH];
__device__ __half g_hs [(size_t)NB * TT * HH];

typedef unsigned long long u64;

__device__ __forceinline__ u64 fma2(u64 a, u64 b, u64 c) {
    u64 d;
    asm("fma.rn.f32x2 %0, %1, %2, %3;" : "=l"(d) : "l"(a), "l"(b), "l"(c));
    return d;
}
__device__ __forceinline__ u64 dup2(float w) {
    unsigned r = __float_as_uint(w);
    u64 d;
    asm("mov.b64 %0, {%1, %1};" : "=l"(d) : "r"(r));
    return d;
}
__device__ __forceinline__ float2 unpk(u64 a) {
    unsigned lo, hi;
    asm("mov.b64 {%0, %1}, %2;" : "=r"(lo), "=r"(hi) : "l"(a));
    return make_float2(__uint_as_float(lo), __uint_as_float(hi));
}
__device__ __forceinline__ float sigf(float x) {
    return __fdividef(1.f, 1.f + __expf(-x));
}
__device__ __forceinline__ float tanh_f(float x) {
    return 2.f * sigf(2.f * x) - 1.f;
}

__global__ void prep_kernel(const float* __restrict__ eWih, const float* __restrict__ eWhh,
                            const float* __restrict__ dWhh, const float* __restrict__ f1W) {
    int i = blockIdx.x * blockDim.x + threadIdx.x;
    if (i >= (HH / 2) * HH) return;
    int k2 = i >> 8, j = i & 255;
    int k = 2 * k2;
    g_hP4[i] = make_float4(eWhh[(size_t)j * HH + k],       eWhh[(size_t)(j + HH) * HH + k],
                           eWhh[(size_t)j * HH + k + 1],   eWhh[(size_t)(j + HH) * HH + k + 1]);
    g_hN2[i] = make_float2(eWhh[(size_t)(j + 2 * HH) * HH + k],
                           eWhh[(size_t)(j + 2 * HH) * HH + k + 1]);
    g_dP4[i] = make_float4(dWhh[(size_t)j * HH + k],       dWhh[(size_t)(j + HH) * HH + k],
                           dWhh[(size_t)j * HH + k + 1],   dWhh[(size_t)(j + HH) * HH + k + 1]);
    g_dN2[i] = make_float2(dWhh[(size_t)(j + 2 * HH) * HH + k],
                           dWhh[(size_t)(j + 2 * HH) * HH + k + 1]);
    g_W12[i] = make_float2(f1W[(size_t)j * HH + k], f1W[(size_t)j * HH + k + 1]);
    if (k2 < FF / 2) {
        g_eP4[k2 * HH + j] = make_float4(
            eWih[(size_t)j * FF + k],     eWih[(size_t)(j + HH) * FF + k],
            eWih[(size_t)j * FF + k + 1], eWih[(size_t)(j + HH) * FF + k + 1]);
        g_eN2[k2 * HH + j] = make_float2(
            eWih[(size_t)(j + 2 * HH) * FF + k], eWih[(size_t)(j + 2 * HH) * FF + k + 1]);
    }
}

struct SM {
    float hti[2][HH][ROWP];   // transposed h tiles [k][b]; decoder: [1]=ctx, [0]=hd
    float xti[2][FF][ROWP];   // double-buffered transposed x tile
    float A[BT][TT];
    float C[BT][TT];
    float ww[BT][TT];
    float ctxp[4][BT][HH];
    float wpart[16][8];
    float prevs[BT];
};

__global__ void __launch_bounds__(NTHR, 1)
forecaster_kernel(
    const float* __restrict__ x,     const float* __restrict__ h0,
    const float* __restrict__ ebih,  const float* __restrict__ ebhh,
    const float* __restrict__ dWih,  const float* __restrict__ dbih,
    const float* __restrict__ dbhh,  const float* __restrict__ aWq,
    const float* __restrict__ abq,   const float* __restrict__ f1b,
    const float* __restrict__ f2W,   const float* __restrict__ f2b,
    float* __restrict__ out)
{
    extern __shared__ char smraw[];
    SM* sm = (SM*)smraw;
    const int tid  = threadIdx.x, wid = tid >> 5, lane = tid & 31;
    const int j     = tid & 255;
    const int bh    = tid >> 8;
    const int bbase = bh * 8;
    const int b0    = blockIdx.x * BT;

    float hreg[8];
    #pragma unroll
    for (int bb = 0; bb < 8; bb++) {
        float v = h0[(size_t)(b0 + bbase + bb) * HH + j];
        hreg[bb] = v;
        sm->hti[0][j][bbase + bb] = v;
    }
    {   // stage x for t=0
        int b = tid >> 5, k2l = (tid & 31) * 2;
        float2 xv = *(const float2*)&x[(size_t)(b0 + b) * TT * FF + k2l];
        sm->xti[0][k2l][b] = xv.x; sm->xti[0][k2l + 1][b] = xv.y;
    }
    const float ebR  = ebih[j]          + ebhh[j];
    const float ebZ  = ebih[j + HH]     + ebhh[j + HH];
    const float ebNi = ebih[j + 2 * HH];
    const float ebNh = ebhh[j + 2 * HH];

    // ======================= ENCODER =======================
    int cur = 0;
    for (int t = 0; t < TT; t++) {
        __syncthreads();
        {   // stage x for t+1 into the other buffer
            int tn = (t + 1 < TT) ? t + 1 : t;
            int b = tid >> 5, k2l = (tid & 31) * 2;
            float2 xv = *(const float2*)&x[((size_t)(b0 + b) * TT + tn) * FF + k2l];
            sm->xti[(t + 1) & 1][k2l][b] = xv.x;
            sm->xti[(t + 1) & 1][k2l + 1][b] = xv.y;
        }

        u64 aR[4], aZ[4], aN[4];
        #pragma unroll
        for (int p = 0; p < 4; p++) { aR[p] = 0; aZ[p] = 0; aN[p] = 0; }

        // gi = x_t @ Wih^T  (packed, 2 k-rows per iter)
        const float4* eP = g_eP4 + j;
        const float2* eN = g_eN2 + j;
        const float  (*xcur)[ROWP] = sm->xti[t & 1];
        #pragma unroll 4
        for (int k2 = 0; k2 < FF / 2; k2++) {
            float4 w4 = eP[k2 * HH];
            float2 n2 = eN[k2 * HH];
            u64 wr0 = dup2(w4.x), wz0 = dup2(w4.y), wn0 = dup2(n2.x);
            u64 wr1 = dup2(w4.z), wz1 = dup2(w4.w), wn1 = dup2(n2.y);
            ulonglong2 h0a = *(const ulonglong2*)&xcur[2 * k2][bbase];
            ulonglong2 h0b = *(const ulonglong2*)&xcur[2 * k2][bbase + 4];
            ulonglong2 h1a = *(const ulonglong2*)&xcur[2 * k2 + 1][bbase];
            ulonglong2 h1b = *(const ulonglong2*)&xcur[2 * k2 + 1][bbase + 4];
            aR[0] = fma2(wr0, h0a.x, aR[0]); aR[0] = fma2(wr1, h1a.x, aR[0]);
            aZ[0] = fma2(wz0, h0a.x, aZ[0]); aZ[0] = fma2(wz1, h1a.x, aZ[0]);
            aN[0] = fma2(wn0, h0a.x, aN[0]); aN[0] = fma2(wn1, h1a.x, aN[0]);
            aR[1] = fma2(wr0, h0a.y, aR[1]); aR[1] = fma2(wr1, h1a.y, aR[1]);
            aZ[1] = fma2(wz0, h0a.y, aZ[1]); aZ[1] = fma2(wz1, h1a.y, aZ[1]);
            aN[1] = fma2(wn0, h0a.y, aN[1]); aN[1] = fma2(wn1, h1a.y, aN[1]);
            aR[2] = fma2(wr0, h0b.x, aR[2]); aR[2] = fma2(wr1, h1b.x, aR[2]);
            aZ[2] = fma2(wz0, h0b.x, aZ[2]); aZ[2] = fma2(wz1, h1b.x, aZ[2]);
            aN[2] = fma2(wn0, h0b.x, aN[2]); aN[2] = fma2(wn1, h1b.x, aN[2]);
            aR[3] = fma2(wr0, h0b.y, aR[3]); aR[3] = fma2(wr1, h1b.y, aR[3]);
            aZ[3] = fma2(wz0, h0b.y, aZ[3]); aZ[3] = fma2(wz1, h1b.y, aZ[3]);
            aN[3] = fma2(wn0, h0b.y, aN[3]); aN[3] = fma2(wn1, h1b.y, aN[3]);
        }
        u64 ni[4];
        #pragma unroll
        for (int p = 0; p < 4; p++) { ni[p] = aN[p]; aN[p] = 0; }

        // gh = h @ Whh^T
        const float4* hP = g_hP4 + j;
        const float2* hN = g_hN2 + j;
        const float  (*hcur)[ROWP] = sm->hti[cur];
        #pragma unroll 4
        for (int k2 = 0; k2 < HH / 2; k2++) {
            float4 w4 = hP[k2 * HH];
            float2 n2 = hN[k2 * HH];
            u64 wr0 = dup2(w4.x), wz0 = dup2(w4.y), wn0 = dup2(n2.x);
            u64 wr1 = dup2(w4.z), wz1 = dup2(w4.w), wn1 = dup2(n2.y);
            ulonglong2 h0a = *(const ulonglong2*)&hcur[2 * k2][bbase];
            ulonglong2 h0b = *(const ulonglong2*)&hcur[2 * k2][bbase + 4];
            ulonglong2 h1a = *(const ulonglong2*)&hcur[2 * k2 + 1][bbase];
            ulonglong2 h1b = *(const ulonglong2*)&hcur[2 * k2 + 1][bbase + 4];
            aR[0] = fma2(wr0, h0a.x, aR[0]); aR[0] = fma2(wr1, h1a.x, aR[0]);
            aZ[0] = fma2(wz0, h0a.x, aZ[0]); aZ[0] = fma2(wz1, h1a.x, aZ[0]);
            aN[0] = fma2(wn0, h0a.x, aN[0]); aN[0] = fma2(wn1, h1a.x, aN[0]);
            aR[1] = fma2(wr0, h0a.y, aR[1]); aR[1] = fma2(wr1, h1a.y, aR[1]);
            aZ[1] = fma2(wz0, h0a.y, aZ[1]); aZ[1] = fma2(wz1, h1a.y, aZ[1]);
            aN[1] = fma2(wn0, h0a.y, aN[1]); aN[1] = fma2(wn1, h1a.y, aN[1]);
            aR[2] = fma2(wr0, h0b.x, aR[2]); aR[2] = fma2(wr1, h1b.x, aR[2]);
            aZ[2] = fma2(wz0, h0b.x, aZ[2]); aZ[2] = fma2(wz1, h1b.x, aZ[2]);
            aN[2] = fma2(wn0, h0b.x, aN[2]); aN[2] = fma2(wn1, h1b.x, aN[2]);
            aR[3] = fma2(wr0, h0b.y, aR[3]); aR[3] = fma2(wr1, h1b.y, aR[3]);
            aZ[3] = fma2(wz0, h0b.y, aZ[3]); aZ[3] = fma2(wz1, h1b.y, aZ[3]);
            aN[3] = fma2(wn0, h0b.y, aN[3]); aN[3] = fma2(wn1, h1b.y, aN[3]);
        }

        const int nxt = cur ^ 1;
        #pragma unroll
        for (int p = 0; p < 4; p++) {
            float2 r2 = unpk(aR[p]), z2 = unpk(aZ[p]);
            float2 nh2 = unpk(aN[p]), ni2 = unpk(ni[p]);
            {
                float r = sigf(r2.x + ebR), z = sigf(z2.x + ebZ);
                float n = tanh_f(ni2.x + ebNi + r * (nh2.x + ebNh));
                hreg[2 * p] = (1.f - z) * n + z * hreg[2 * p];
            }
            {
                float r = sigf(r2.y + ebR), z = sigf(z2.y + ebZ);
                float n = tanh_f(ni2.y + ebNi + r * (nh2.y + ebNh));
                hreg[2 * p + 1] = (1.f - z) * n + z * hreg[2 * p + 1];
            }
        }
        *(float4*)&sm->hti[nxt][j][bbase] =
            make_float4(hreg[0], hreg[1], hreg[2], hreg[3]);
        *(float4*)&sm->hti[nxt][j][bbase + 4] =
            make_float4(hreg[4], hreg[5], hreg[6], hreg[7]);
        #pragma unroll
        for (int bb = 0; bb < 8; bb++) {
            size_t off = ((size_t)(b0 + bbase + bb) * TT + t) * HH + j;
            g_hsf[off] = hreg[bb];
            g_hs[off]  = __float2half(hreg[bb]);
        }
        cur = nxt;
    }
    __syncthreads();

    // ---- A/C pass: A[b][t]=Wq.h, C[b][t]=bq.h from fp32 scratch ----
    {
        int b = wid;   // warp per batch row
        float wq[8], bq[8];
        {
            float4 a0 = *(const float4*)&aWq[lane * 8];
            float4 a1 = *(const float4*)&aWq[lane * 8 + 4];
            float4 c0 = *(const float4*)&abq[lane * 8];
            float4 c1 = *(const float4*)&abq[lane * 8 + 4];
            wq[0]=a0.x; wq[1]=a0.y; wq[2]=a0.z; wq[3]=a0.w;
            wq[4]=a1.x; wq[5]=a1.y; wq[6]=a1.z; wq[7]=a1.w;
            bq[0]=c0.x; bq[1]=c0.y; bq[2]=c0.z; bq[3]=c0.w;
            bq[4]=c1.x; bq[5]=c1.y; bq[6]=c1.z; bq[7]=c1.w;
        }
        const float* hb = g_hsf + (size_t)(b0 + b) * TT * HH + lane * 8;
        for (int t = 0; t < TT; t++) {
            float4 h0v = *(const float4*)(hb + (size_t)t * HH);
            float4 h1v = *(const float4*)(hb + (size_t)t * HH + 4);
            float pa = wq[0]*h0v.x + wq[1]*h0v.y + wq[2]*h0v.z + wq[3]*h0v.w
                     + wq[4]*h1v.x + wq[5]*h1v.y + wq[6]*h1v.z + wq[7]*h1v.w;
            float pc = bq[0]*h0v.x + bq[1]*h0v.y + bq[2]*h0v.z + bq[3]*h0v.w
                     + bq[4]*h1v.x + bq[5]*h1v.y + bq[6]*h1v.z + bq[7]*h1v.w;
            #pragma unroll
            for (int off = 16; off; off >>= 1) {
                pa += __shfl_xor_sync(0xffffffffu, pa, off);
                pc += __shfl_xor_sync(0xffffffffu, pc, off);
            }
            if (lane == 0) { sm->A[b][t] = pa; sm->C[b][t] = pc; }
        }
    }

    // ======================= DECODER =======================
    const float dbR  = dbih[j]          + dbhh[j];
    const float dbZ  = dbih[j + HH]     + dbhh[j + HH];
    const float dbNi = dbih[j + 2 * HH];
    const float dbNh = dbhh[j + 2 * HH];
    const float wiR  = dWih[j];
    const float wiZ  = dWih[j + HH];
    const float wiN  = dWih[j + 2 * HH];
    const float f2w  = f2W[j];
    const float f1bv = f1b[j];
    const float f2b0 = f2b[0];

    if (tid < BT)
        sm->prevs[tid] = x[((size_t)(b0 + tid) * TT + (TT - 1)) * FF];
    __syncthreads();

    const float scale = 0.0625f;
    for (int s = 0; s < OUTL; s++) {
        // scores + softmax: warp wid handles batch row b=wid
        {
            int b = wid;
            float p = sm->prevs[b];
            float sc[4]; float mx = -1e30f;
            #pragma unroll
            for (int i = 0; i < 4; i++) {
                int tt2 = lane + 32 * i;
                sc[i] = (p * sm->A[b][tt2] + sm->C[b][tt2]) * scale;
                mx = fmaxf(mx, sc[i]);
            }
            #pragma unroll
            for (int off = 16; off; off >>= 1)
                mx = fmaxf(mx, __shfl_xor_sync(0xffffffffu, mx, off));
            float sum = 0.f;
            #pragma unroll
            for (int i = 0; i < 4; i++) { sc[i] = __expf(sc[i] - mx); sum += sc[i]; }
            #pragma unroll
            for (int off = 16; off; off >>= 1)
                sum += __shfl_xor_sync(0xffffffffu, sum, off);
            float inv = __fdividef(1.f, sum);
            #pragma unroll
            for (int i = 0; i < 4; i++) sm->ww[b][lane + 32 * i] = sc[i] * inv;
        }
        __syncthreads();

        // ctx = sum_t w[t]*hs[t] over 4 t-quarters (fp16 stream)
        {
            int th = tid >> 7, c = (tid & 127) * 2;
            float2 acc[BT];
            #pragma unroll
            for (int b = 0; b < BT; b++) acc[b] = make_float2(0.f, 0.f);
            const __half* base = g_hs + ((size_t)b0 * TT + th * 32) * HH + c;
            #pragma unroll 1
            for (int ti = 0; ti < 32; ti++) {
                int tt2 = th * 32 + ti;
                const __half* pb = base + (size_t)ti * HH;
                #pragma unroll
                for (int b = 0; b < BT; b++) {
                    float wv = sm->ww[b][tt2];
                    __half2 hv = *(const __half2*)(pb + (size_t)b * TT * HH);
                    float2 f = __half22float2(hv);
                    acc[b].x = fmaf(wv, f.x, acc[b].x);
                    acc[b].y = fmaf(wv, f.y, acc[b].y);
                }
            }
            #pragma unroll
            for (int b = 0; b < BT; b++)
                *(float2*)&sm->ctxp[th][b][c] = acc[b];
        }
        __syncthreads();
        {
            #pragma unroll
            for (int bb = 0; bb < 8; bb++) {
                int b = bbase + bb;
                sm->hti[1][j][b] = sm->ctxp[0][b][j] + sm->ctxp[1][b][j]
                                 + sm->ctxp[2][b][j] + sm->ctxp[3][b][j];
            }
        }
        __syncthreads();

        // decoder GRU: gh = ctx @ dWhh^T (packed)
        {
            u64 aR[4], aZ[4], aN[4];
            #pragma unroll
            for (int p = 0; p < 4; p++) { aR[p] = 0; aZ[p] = 0; aN[p] = 0; }
            const float4* dP = g_dP4 + j;
            const float2* dN = g_dN2 + j;
            const float (*ccur)[ROWP] = sm->hti[1];
            #pragma unroll 4
            for (int k2 = 0; k2 < HH / 2; k2++) {
                float4 w4 = dP[k2 * HH];
                float2 n2 = dN[k2 * HH];
                u64 wr0 = dup2(w4.x), wz0 = dup2(w4.y), wn0 = dup2(n2.x);
                u64 wr1 = dup2(w4.z), wz1 = dup2(w4.w), wn1 = dup2(n2.y);
                ulonglong2 h0a = *(const ulonglong2*)&ccur[2 * k2][bbase];
                ulonglong2 h0b = *(const ulonglong2*)&ccur[2 * k2][bbase + 4];
                ulonglong2 h1a = *(const ulonglong2*)&ccur[2 * k2 + 1][bbase];
                ulonglong2 h1b = *(const ulonglong2*)&ccur[2 * k2 + 1][bbase + 4];
                aR[0] = fma2(wr0, h0a.x, aR[0]); aR[0] = fma2(wr1, h1a.x, aR[0]);
                aZ[0] = fma2(wz0, h0a.x, aZ[0]); aZ[0] = fma2(wz1, h1a.x, aZ[0]);
                aN[0] = fma2(wn0, h0a.x, aN[0]); aN[0] = fma2(wn1, h1a.x, aN[0]);
                aR[1] = fma2(wr0, h0a.y, aR[1]); aR[1] = fma2(wr1, h1a.y, aR[1]);
                aZ[1] = fma2(wz0, h0a.y, aZ[1]); aZ[1] = fma2(wz1, h1a.y, aZ[1]);
                aN[1] = fma2(wn0, h0a.y, aN[1]); aN[1] = fma2(wn1, h1a.y, aN[1]);
                aR[2] = fma2(wr0, h0b.x, aR[2]); aR[2] = fma2(wr1, h1b.x, aR[2]);
                aZ[2] = fma2(wz0, h0b.x, aZ[2]); aZ[2] = fma2(wz1, h1b.x, aZ[2]);
                aN[2] = fma2(wn0, h0b.x, aN[2]); aN[2] = fma2(wn1, h1b.x, aN[2]);
                aR[3] = fma2(wr0, h0b.y, aR[3]); aR[3] = fma2(wr1, h1b.y, aR[3]);
                aZ[3] = fma2(wz0, h0b.y, aZ[3]); aZ[3] = fma2(wz1, h1b.y, aZ[3]);
                aN[3] = fma2(wn0, h0b.y, aN[3]); aN[3] = fma2(wn1, h1b.y, aN[3]);
            }
            float hdv[8];
            #pragma unroll
            for (int p = 0; p < 4; p++) {
                float2 r2 = unpk(aR[p]), z2 = unpk(aZ[p]), nh2 = unpk(aN[p]);
                {
                    int bb = 2 * p; float pv = sm->prevs[bbase + bb];
                    float r = sigf(r2.x + pv * wiR + dbR);
                    float z = sigf(z2.x + pv * wiZ + dbZ);
                    float n = tanh_f(pv * wiN + dbNi + r * (nh2.x + dbNh));
                    hdv[bb] = (1.f - z) * n + z * sm->hti[1][j][bbase + bb];
                }
                {
                    int bb = 2 * p + 1; float pv = sm->prevs[bbase + bb];
                    float r = sigf(r2.y + pv * wiR + dbR);
                    float z = sigf(z2.y + pv * wiZ + dbZ);
                    float n = tanh_f(pv * wiN + dbNi + r * (nh2.y + dbNh));
                    hdv[bb] = (1.f - z) * n + z * sm->hti[1][j][bbase + bb];
                }
            }
            __syncthreads();
            *(float4*)&sm->hti[0][j][bbase] =
                make_float4(hdv[0], hdv[1], hdv[2], hdv[3]);
            *(float4*)&sm->hti[0][j][bbase + 4] =
                make_float4(hdv[4], hdv[5], hdv[6], hdv[7]);
        }
        __syncthreads();

        // fc1(relu) + fc2 (packed f1W)
        {
            u64 aF[4];
            #pragma unroll
            for (int p = 0; p < 4; p++) aF[p] = 0;
            const float2* w1 = g_W12 + j;
            const float (*hdc)[ROWP] = sm->hti[0];
            #pragma unroll 4
            for (int k2 = 0; k2 < HH / 2; k2++) {
                float2 w2 = w1[k2 * HH];
                u64 wa = dup2(w2.x), wb = dup2(w2.y);
                ulonglong2 h0a = *(const ulonglong2*)&hdc[2 * k2][bbase];
                ulonglong2 h0b = *(const ulonglong2*)&hdc[2 * k2][bbase + 4];
                ulonglong2 h1a = *(const ulonglong2*)&hdc[2 * k2 + 1][bbase];
                ulonglong2 h1b = *(const ulonglong2*)&hdc[2 * k2 + 1][bbase + 4];
                aF[0] = fma2(wa, h0a.x, aF[0]); aF[0] = fma2(wb, h1a.x, aF[0]);
                aF[1] = fma2(wa, h0a.y, aF[1]); aF[1] = fma2(wb, h1a.y, aF[1]);
                aF[2] = fma2(wa, h0b.x, aF[2]); aF[2] = fma2(wb, h1b.x, aF[2]);
                aF[3] = fma2(wa, h0b.y, aF[3]); aF[3] = fma2(wb, h1b.y, aF[3]);
            }
            #pragma unroll
            for (int p = 0; p < 4; p++) {
                float2 f = unpk(aF[p]);
                float v0 = fmaxf(f.x + f1bv, 0.f) * f2w;
                float v1 = fmaxf(f.y + f1bv, 0.f) * f2w;
                #pragma unroll
                for (int off = 16; off; off >>= 1) {
                    v0 += __shfl_down_sync(0xffffffffu, v0, off);
                    v1 += __shfl_down_sync(0xffffffffu, v1, off);
                }
                if (lane == 0) {
                    sm->wpart[wid][2 * p]     = v0;
                    sm->wpart[wid][2 * p + 1] = v1;
                }
            }
        }
        __syncthreads();
        if (tid < BT) {
            float o = f2b0;
            int wb = (tid >> 3) * 8;
            #pragma unroll
            for (int w = 0; w < 8; w++) o += sm->wpart[wb + w][tid & 7];
            out[(size_t)(b0 + tid) * OUTL + s] = o;
            sm->prevs[tid] = o;
        }
        __syncthreads();
    }
}

extern "C" void kernel_launch(void* const* d_in, const int* in_sizes, int n_in,
                              void* d_out, int out_size) {
    const float* x    = (const float*)d_in[0];
    const float* h0   = (const float*)d_in[1];
    const float* eWih = (const float*)d_in[2];
    const float* eWhh = (const float*)d_in[3];
    const float* ebih = (const float*)d_in[4];
    const float* ebhh = (const float*)d_in[5];
    const float* dWih = (const float*)d_in[6];
    const float* dWhh = (const float*)d_in[7];
    const float* dbih = (const float*)d_in[8];
    const float* dbhh = (const float*)d_in[9];
    const float* aWq  = (const float*)d_in[10];
    const float* abq  = (const float*)d_in[11];
    const float* f1W  = (const float*)d_in[12];
    const float* f1b  = (const float*)d_in[13];
    const float* f2W  = (const float*)d_in[14];
    const float* f2b  = (const float*)d_in[15];
    float* out = (float*)d_out;

    prep_kernel<<<((HH / 2) * HH + 255) / 256, 256>>>(eWih, eWhh, dWhh, f1W);

    size_t shmem = sizeof(SM);
    cudaFuncSetAttribute(forecaster_kernel,
                         cudaFuncAttributeMaxDynamicSharedMemorySize, (int)shmem);
    forecaster_kernel<<<NCTA, NTHR, shmem>>>(
        x, h0, ebih, ebhh, dWih, dbih, dbhh, aWq, abq, f1b, f2W, f2b, out);
}